// round 8
// baseline (speedup 1.0000x reference)
#include <cuda_runtime.h>
#include <cuda_bf16.h>
#include <mma.h>
#include <math.h>
#include <stdint.h>

using namespace nvcuda;

#define NROWS 6144
#define DIM 128
#define WINSZ 10
#define BANDW 21
#define NEMO 7
#define YCOLS 640        // [W_pred | W_suc | W_same | W_diff | w_aggr] * 128
#define MT 128           // GEMM M tile
#define NT 64            // GEMM N tile
#define MTILES 48        // 6144/128
#define NTILES 10        // 640/64
#define LDS_PAD 136      // smem row stride in bf16 elems (128 + 8)

// dynamic smem: Ah(128) + Al(128) + Bh(64) + Bl(64) rows * 136 * 2B
#define WG_SMEM ((128 + 128 + 64 + 64) * LDS_PAD * 2)

// setup kernel block ranges
#define SETUP_PREP_BLKS 768          // 6144*32 / 256
#define SETUP_PACK_BLKS 320          // 5*128*128 / 256
#define SETUP_PACKE_BLKS 128         // 128*256 / 256
#define SETUP_BLKS (SETUP_PREP_BLKS + SETUP_PACK_BLKS + SETUP_PACKE_BLKS)

// ---------------- scratch (device globals; no allocation allowed) ------------
__device__ __align__(16) float g_attn[NROWS * BANDW];
__device__ __align__(16) float g_Y[NROWS * YCOLS];
__device__ __align__(16) float g_Hcat[NROWS * 2 * DIM];
__device__ __align__(16) float g_T[NROWS * DIM];
// bf16 hi/lo splits, row-major, k contiguous
__device__ __align__(16) __nv_bfloat16 g_Ah[NROWS * DIM];        // h1 split
__device__ __align__(16) __nv_bfloat16 g_Al[NROWS * DIM];
__device__ __align__(16) __nv_bfloat16 g_Hh[NROWS * 2 * DIM];    // Hcat split
__device__ __align__(16) __nv_bfloat16 g_Hl[NROWS * 2 * DIM];
__device__ __align__(16) __nv_bfloat16 g_Bh1[YCOLS * DIM];
__device__ __align__(16) __nv_bfloat16 g_Bl1[YCOLS * DIM];
__device__ __align__(16) __nv_bfloat16 g_Bh2[YCOLS * DIM];
__device__ __align__(16) __nv_bfloat16 g_Bl2[YCOLS * DIM];
__device__ __align__(16) __nv_bfloat16 g_Weh[DIM * 2 * DIM];     // we1 split [n=128][k=256]
__device__ __align__(16) __nv_bfloat16 g_Wel[DIM * 2 * DIM];

// ---------------- helpers ----------------------------------------------------
__device__ __forceinline__ void bf_split(float f, uint16_t& h, uint16_t& l) {
    __nv_bfloat16 bh = __float2bfloat16_rn(f);
    float r = f - __bfloat162float(bh);
    __nv_bfloat16 bl = __float2bfloat16_rn(r);
    h = *(uint16_t*)&bh;
    l = *(uint16_t*)&bl;
}
__device__ __forceinline__ void split_store4(char* hp, char* lp, float4 v) {
    uint16_t h0, h1, h2, h3, l0, l1, l2, l3;
    bf_split(v.x, h0, l0); bf_split(v.y, h1, l1);
    bf_split(v.z, h2, l2); bf_split(v.w, h3, l3);
    *(uint2*)hp = make_uint2((uint32_t)h0 | ((uint32_t)h1 << 16),
                             (uint32_t)h2 | ((uint32_t)h3 << 16));
    *(uint2*)lp = make_uint2((uint32_t)l0 | ((uint32_t)l1 << 16),
                             (uint32_t)l2 | ((uint32_t)l3 << 16));
}

// ------- kernel: fused setup (prep x + pack layer weights + pack we1) --------
__global__ void setup_kernel(const float* __restrict__ x,
                             const float* __restrict__ Wp1, const float* __restrict__ Ws1,
                             const float* __restrict__ Wsa1, const float* __restrict__ Wd1,
                             const float* __restrict__ Wag1,
                             const float* __restrict__ Wp2, const float* __restrict__ Ws2,
                             const float* __restrict__ Wsa2, const float* __restrict__ Wd2,
                             const float* __restrict__ Wag2,
                             const float* __restrict__ we1) {
    int blk = blockIdx.x;
    if (blk < SETUP_PREP_BLKS) {
        // prep: x -> Hcat right half fp32 + bf16 hi/lo split
        int t = blk * 256 + threadIdx.x;              // over 6144*32 float4
        int i = t >> 5, q = t & 31;
        float4 v = ((const float4*)x)[t];
        size_t e = (size_t)i * 2 * DIM + DIM + q * 4;
        *(float4*)&g_Hcat[e] = v;
        split_store4((char*)g_Hh + e * 2, (char*)g_Hl + e * 2, v);
    } else if (blk < SETUP_PREP_BLKS + SETUP_PACK_BLKS) {
        // pack layer weights, coalesced reads: t -> (rel, k, d)
        int t = (blk - SETUP_PREP_BLKS) * 256 + threadIdx.x;   // over 5*128*128
        int rel = t >> 14, k = (t >> 7) & 127, d = t & 127;
        const float* s1;
        const float* s2;
        switch (rel) {
            case 0: s1 = Wp1;  s2 = Wp2;  break;
            case 1: s1 = Ws1;  s2 = Ws2;  break;
            case 2: s1 = Wsa1; s2 = Wsa2; break;
            case 3: s1 = Wd1;  s2 = Wd2;  break;
            default: s1 = Wag1; s2 = Wag2; break;
        }
        int widx = (rel * 128 + d) * 128 + k;          // [n=rel*128+d][k]
        uint16_t h, l;
        bf_split(s1[k * DIM + d], h, l);
        *(uint16_t*)&g_Bh1[widx] = h;
        *(uint16_t*)&g_Bl1[widx] = l;
        bf_split(s2[k * DIM + d], h, l);
        *(uint16_t*)&g_Bh2[widx] = h;
        *(uint16_t*)&g_Bl2[widx] = l;
    } else {
        // pack we1 [256][128] -> hi/lo [n=128][k=256], coalesced reads
        int t = (blk - SETUP_PREP_BLKS - SETUP_PACK_BLKS) * 256 + threadIdx.x; // over 128*256
        int k = t >> 7, n = t & 127;
        uint16_t h, l;
        bf_split(we1[t], h, l);                        // we1[k*128+n]
        *(uint16_t*)&g_Weh[n * 256 + k] = h;
        *(uint16_t*)&g_Wel[n * 256 + k] = l;
    }
}

// ---------------- kernel: banded scores + faithful softmax -------------------
__global__ void attn_kernel(const float* __restrict__ x) {
    int warp = threadIdx.x >> 5;
    int lane = threadIdx.x & 31;
    int i = blockIdx.x * 4 + warp;
    if (i >= NROWS) return;

    float xi0 = x[i * DIM + lane];
    float xi1 = x[i * DIM + 32 + lane];
    float xi2 = x[i * DIM + 64 + lane];
    float xi3 = x[i * DIM + 96 + lane];

    float myscore = -3.4e38f;
    #pragma unroll
    for (int l = 0; l < BANDW; l++) {
        int j = i - WINSZ + l;
        if (j >= 0 && j < NROWS) {
            const float* xj = x + (size_t)j * DIM;
            float s = xi0 * xj[lane] + xi1 * xj[32 + lane]
                    + xi2 * xj[64 + lane] + xi3 * xj[96 + lane];
            #pragma unroll
            for (int off = 16; off; off >>= 1) s += __shfl_xor_sync(~0u, s, off);
            if (lane == l) myscore = s;
        }
    }
    int jl = i - WINSZ + lane;
    bool valid = (lane < BANDW) && (jl >= 0) && (jl < NROWS);
    float m = valid ? myscore : -3.4e38f;
    #pragma unroll
    for (int off = 16; off; off >>= 1) m = fmaxf(m, __shfl_xor_sync(~0u, m, off));
    m = fmaxf(m, 0.0f);
    float e = valid ? expf(myscore - m) : 0.0f;
    float sum = e;
    #pragma unroll
    for (int off = 16; off; off >>= 1) sum += __shfl_xor_sync(~0u, sum, off);
    int lo = max(0, i - WINSZ), hi = min(NROWS - 1, i + WINSZ);
    int nband = hi - lo + 1;
    float den = sum + (float)(NROWS - nband) * expf(-m);
    if (lane < BANDW) g_attn[i * BANDW + lane] = e / den;
}

// ------- kernel: wmma bf16-split GEMM  C[M x ...] = A @ B^T ------------------
template <int KCHUNKS, bool EPI>
__global__ void __launch_bounds__(256, 2)
wgemm_kernel(const __nv_bfloat16* __restrict__ Ah, const __nv_bfloat16* __restrict__ Al,
             int lda4,
             const __nv_bfloat16* __restrict__ Bh, const __nv_bfloat16* __restrict__ Bl,
             int ldb4,
             float* __restrict__ C, int ldc, const float* __restrict__ bias) {
    extern __shared__ __nv_bfloat16 sm[];
    __nv_bfloat16* Ah_s = sm;                               // 128 x 136
    __nv_bfloat16* Al_s = Ah_s + 128 * LDS_PAD;
    __nv_bfloat16* Bh_s = Al_s + 128 * LDS_PAD;             // 64 x 136
    __nv_bfloat16* Bl_s = Bh_s + 64 * LDS_PAD;

    int tid = threadIdx.x;
    int ntile = blockIdx.x, mtile = blockIdx.y;
    int warp = tid >> 5, lane = tid & 31;
    int wm = warp & 3;            // m offset = wm*32
    int wn = warp >> 2;           // n offset = wn*32

    wmma::fragment<wmma::accumulator, 16, 16, 16, float> acc[2][2];
    #pragma unroll
    for (int u = 0; u < 2; u++)
        #pragma unroll
        for (int v = 0; v < 2; v++) wmma::fill_fragment(acc[u][v], 0.0f);

    const float4* ga_h = (const float4*)Ah;
    const float4* ga_l = (const float4*)Al;
    const float4* gb_h = (const float4*)Bh;
    const float4* gb_l = (const float4*)Bl;

    #pragma unroll
    for (int kc = 0; kc < KCHUNKS; kc++) {
        if (kc) __syncthreads();
        #pragma unroll
        for (int it = 0; it < 8; it++) {                    // A pair: 128x16 float4
            int v = tid + it * 256;
            int row = v >> 4, q = v & 15;
            int gi = (mtile * MT + row) * lda4 + kc * 16 + q;
            *(float4*)&Ah_s[row * LDS_PAD + q * 8] = ga_h[gi];
            *(float4*)&Al_s[row * LDS_PAD + q * 8] = ga_l[gi];
        }
        #pragma unroll
        for (int it = 0; it < 4; it++) {                    // B pair: 64x16 float4
            int v = tid + it * 256;
            int row = v >> 4, q = v & 15;
            int gi = (ntile * NT + row) * ldb4 + kc * 16 + q;
            *(float4*)&Bh_s[row * LDS_PAD + q * 8] = gb_h[gi];
            *(float4*)&Bl_s[row * LDS_PAD + q * 8] = gb_l[gi];
        }
        __syncthreads();

        #pragma unroll
        for (int ks = 0; ks < 8; ks++) {
            wmma::fragment<wmma::matrix_a, 16, 16, 16, __nv_bfloat16, wmma::row_major> ah[2], al[2];
            wmma::fragment<wmma::matrix_b, 16, 16, 16, __nv_bfloat16, wmma::col_major> bh[2], bl[2];
            #pragma unroll
            for (int u = 0; u < 2; u++) {
                int r = wm * 32 + u * 16;
                wmma::load_matrix_sync(ah[u], &Ah_s[r * LDS_PAD + ks * 16], LDS_PAD);
                wmma::load_matrix_sync(al[u], &Al_s[r * LDS_PAD + ks * 16], LDS_PAD);
            }
            #pragma unroll
            for (int v = 0; v < 2; v++) {
                int r = wn * 32 + v * 16;
                wmma::load_matrix_sync(bh[v], &Bh_s[r * LDS_PAD + ks * 16], LDS_PAD);
                wmma::load_matrix_sync(bl[v], &Bl_s[r * LDS_PAD + ks * 16], LDS_PAD);
            }
            #pragma unroll
            for (int u = 0; u < 2; u++)
                #pragma unroll
                for (int v = 0; v < 2; v++) {
                    wmma::mma_sync(acc[u][v], ah[u], bh[v], acc[u][v]);
                    wmma::mma_sync(acc[u][v], ah[u], bl[v], acc[u][v]);
                    wmma::mma_sync(acc[u][v], al[u], bh[v], acc[u][v]);
                }
        }
    }

    if (!EPI) {
        #pragma unroll
        for (int u = 0; u < 2; u++)
            #pragma unroll
            for (int v = 0; v < 2; v++) {
                int row = mtile * MT + wm * 32 + u * 16;
                int col = ntile * NT + wn * 32 + v * 16;
                wmma::store_matrix_sync(&C[(size_t)row * ldc + col], acc[u][v],
                                        ldc, wmma::mem_row_major);
            }
    } else {
        __syncthreads();
        float* stage = (float*)sm + warp * 1024;
        #pragma unroll
        for (int u = 0; u < 2; u++)
            #pragma unroll
            for (int v = 0; v < 2; v++)
                wmma::store_matrix_sync(&stage[u * 16 * 32 + v * 16], acc[u][v],
                                        32, wmma::mem_row_major);
        int row = mtile * MT + wm * 32 + lane;
        int colbase = ntile * NT + wn * 32;
        #pragma unroll
        for (int c = 0; c < 32; c += 4) {
            float4 val = *(float4*)&stage[lane * 32 + c];
            float4 bv = *(const float4*)&bias[colbase + c];
            val.x = fmaxf(val.x + bv.x, 0.0f);
            val.y = fmaxf(val.y + bv.y, 0.0f);
            val.z = fmaxf(val.z + bv.z, 0.0f);
            val.w = fmaxf(val.w + bv.w, 0.0f);
            *(float4*)&C[(size_t)row * ldc + colbase + c] = val;
        }
    }
}

// ------- kernel: banded combine + aggr + relu (warp/row, float4) -------------
template <int MODE>
__global__ void combine_kernel(const int* __restrict__ spk) {
    int warp = threadIdx.x >> 5, lane = threadIdx.x & 31;
    int i = blockIdx.x * 8 + warp;
    if (i >= NROWS) return;

    float a_l = 0.0f;
    int off_l = 0;
    if (lane < BANDW) {
        int j = i - WINSZ + lane;
        if (j >= 0 && j < NROWS) {
            a_l = g_attn[i * BANDW + lane];
            bool same = (spk[j] == spk[i]);
            bool pred = (lane >= WINSZ);
            int col = same ? (pred ? 0 : 1) : (pred ? 2 : 3);
            off_l = j * YCOLS + col * DIM;
        }
    }

    const float4* Yv = (const float4*)g_Y;
    float da = __shfl_sync(~0u, a_l, WINSZ);
    float4 yv = Yv[(i * YCOLS + 4 * DIM) / 4 + lane];
    float4 acc = make_float4(da * yv.x, da * yv.y, da * yv.z, da * yv.w);

    #pragma unroll
    for (int l = 0; l < BANDW; l++) {
        float a = __shfl_sync(~0u, a_l, l);
        int off = __shfl_sync(~0u, off_l, l);
        if (a != 0.0f) {
            float4 y = Yv[off / 4 + lane];
            acc.x += a * y.x; acc.y += a * y.y;
            acc.z += a * y.z; acc.w += a * y.w;
        }
    }
    acc.x = fmaxf(acc.x, 0.0f); acc.y = fmaxf(acc.y, 0.0f);
    acc.z = fmaxf(acc.z, 0.0f); acc.w = fmaxf(acc.w, 0.0f);

    if (MODE == 0) {
        size_t e = (size_t)i * DIM + lane * 4;
        split_store4((char*)g_Ah + e * 2, (char*)g_Al + e * 2, acc);
    } else {
        size_t e = (size_t)i * 2 * DIM + lane * 4;
        *(float4*)&g_Hcat[e] = acc;
        split_store4((char*)g_Hh + e * 2, (char*)g_Hl + e * 2, acc);
    }
}

// ---------------- kernel: emotion / sentiment heads --------------------------
__global__ void head_kernel(const float* __restrict__ we2, const float* __restrict__ be2,
                            const float* __restrict__ ws, const float* __restrict__ bs,
                            float* __restrict__ out) {
    int warp = threadIdx.x >> 5, lane = threadIdx.x & 31;
    int i = blockIdx.x * 8 + warp;
    if (i >= NROWS) return;

    float tv[4];
    #pragma unroll
    for (int c = 0; c < 4; c++) tv[c] = g_T[i * DIM + c * 32 + lane];
    float hv[8];
    #pragma unroll
    for (int c = 0; c < 8; c++) hv[c] = g_Hcat[i * 2 * DIM + c * 32 + lane];

    #pragma unroll
    for (int e = 0; e < NEMO; e++) {
        float s = 0.0f;
        #pragma unroll
        for (int c = 0; c < 4; c++) s += tv[c] * we2[(c * 32 + lane) * NEMO + e];
        #pragma unroll
        for (int off = 16; off; off >>= 1) s += __shfl_xor_sync(~0u, s, off);

        float s2 = 0.0f;
        #pragma unroll
        for (int c = 0; c < 8; c++) s2 += hv[c] * ws[(c * 32 + lane) * NEMO + e];
        #pragma unroll
        for (int off = 16; off; off >>= 1) s2 += __shfl_xor_sync(~0u, s2, off);

        if (lane == 0) {
            out[i * NEMO + e] = s + be2[e];
            out[NROWS * NEMO + i * NEMO + e] = s2 + bs[e];
        }
    }
}

// -----------------------------------------------------------------------------
extern "C" void kernel_launch(void* const* d_in, const int* in_sizes, int n_in,
                              void* d_out, int out_size) {
    const float* x       = (const float*)d_in[0];
    const int*   spk     = (const int*)d_in[1];
    const float* Wp1     = (const float*)d_in[2];
    const float* Ws1     = (const float*)d_in[3];
    const float* Wsa1    = (const float*)d_in[4];
    const float* Wd1     = (const float*)d_in[5];
    const float* Wp2     = (const float*)d_in[6];
    const float* Ws2     = (const float*)d_in[7];
    const float* Wsa2    = (const float*)d_in[8];
    const float* Wd2     = (const float*)d_in[9];
    const float* Wag1    = (const float*)d_in[10];
    const float* Wag2    = (const float*)d_in[11];
    const float* we1     = (const float*)d_in[12];
    const float* be1     = (const float*)d_in[13];
    const float* we2     = (const float*)d_in[14];
    const float* be2     = (const float*)d_in[15];
    const float* wsw     = (const float*)d_in[16];
    const float* bsb     = (const float*)d_in[17];
    float* out = (float*)d_out;

    cudaFuncSetAttribute(wgemm_kernel<1, false>,
                         cudaFuncAttributeMaxDynamicSharedMemorySize, WG_SMEM);
    cudaFuncSetAttribute(wgemm_kernel<2, true>,
                         cudaFuncAttributeMaxDynamicSharedMemorySize, WG_SMEM);

    __nv_bfloat16 *ah, *al, *hh, *hl, *bh1, *bl1, *bh2, *bl2, *weh, *wel;
    float *yp, *tp;
    cudaGetSymbolAddress((void**)&ah, g_Ah);
    cudaGetSymbolAddress((void**)&al, g_Al);
    cudaGetSymbolAddress((void**)&hh, g_Hh);
    cudaGetSymbolAddress((void**)&hl, g_Hl);
    cudaGetSymbolAddress((void**)&bh1, g_Bh1);
    cudaGetSymbolAddress((void**)&bl1, g_Bl1);
    cudaGetSymbolAddress((void**)&bh2, g_Bh2);
    cudaGetSymbolAddress((void**)&bl2, g_Bl2);
    cudaGetSymbolAddress((void**)&weh, g_Weh);
    cudaGetSymbolAddress((void**)&wel, g_Wel);
    cudaGetSymbolAddress((void**)&yp, g_Y);
    cudaGetSymbolAddress((void**)&tp, g_T);

    // fork a side stream for attn (needed only by combine, not by GEMM-1)
    cudaStream_t s2;
    cudaStreamCreateWithFlags(&s2, cudaStreamNonBlocking);
    cudaEvent_t eFork, eJoin;
    cudaEventCreateWithFlags(&eFork, cudaEventDisableTiming);
    cudaEventCreateWithFlags(&eJoin, cudaEventDisableTiming);

    cudaEventRecord(eFork, 0);
    cudaStreamWaitEvent(s2, eFork, 0);
    attn_kernel<<<NROWS / 4, 128, 0, s2>>>(x);
    cudaEventRecord(eJoin, s2);

    // main stream: setup + GEMM-1 run concurrently with attn
    setup_kernel<<<SETUP_BLKS, 256>>>(x, Wp1, Ws1, Wsa1, Wd1, Wag1,
                                      Wp2, Ws2, Wsa2, Wd2, Wag2, we1);
    // Y = x @ Wcat1   (A = right half of Hcat split, lda = 256)
    wgemm_kernel<1, false><<<dim3(NTILES, MTILES), 256, WG_SMEM>>>(
        hh + DIM, hl + DIM, 32, bh1, bl1, 16, yp, YCOLS, nullptr);

    cudaStreamWaitEvent(0, eJoin, 0);     // attn must be done before combine
    combine_kernel<0><<<NROWS / 8, 256>>>(spk);   // -> g_Ah/g_Al (h1)
    // Y = h1 @ Wcat2
    wgemm_kernel<1, false><<<dim3(NTILES, MTILES), 256, WG_SMEM>>>(
        ah, al, 16, bh2, bl2, 16, yp, YCOLS, nullptr);
    combine_kernel<1><<<NROWS / 8, 256>>>(spk);   // -> Hcat left + split
    // T = relu(Hcat @ we1 + be1)   (K = 256 -> 2 chunks)
    wgemm_kernel<2, true><<<dim3(2, MTILES), 256, WG_SMEM>>>(
        hh, hl, 32, weh, wel, 32, tp, DIM, be1);
    head_kernel<<<NROWS / 8, 256>>>(we2, be2, wsw, bsb, out);
}

// round 10
// speedup vs baseline: 1.4614x; 1.4614x over previous
#include <cuda_runtime.h>
#include <cuda_bf16.h>
#include <mma.h>
#include <math.h>
#include <stdint.h>

using namespace nvcuda;

#define NROWS 6144
#define DIM 128
#define WINSZ 10
#define BANDW 21
#define NEMO 7
#define YCOLS 640        // [W_pred | W_suc | W_same | W_diff | w_aggr] * 128
#define MT 128           // GEMM M tile
#define NT 64            // GEMM N tile
#define MTILES 48        // 6144/128
#define NTILES 10        // 640/64
#define LDS_PAD 136      // smem row stride in bf16 elems (128 + 8)

// dynamic smem: Ah(128) + Al(128) + Bh(64) + Bl(64) rows * 136 * 2B
#define WG_SMEM ((128 + 128 + 64 + 64) * LDS_PAD * 2)

// ---------------- scratch (device globals; no allocation allowed) ------------
__device__ __align__(16) float g_attn[NROWS * BANDW];
__device__ __align__(16) int   g_off[NROWS * BANDW];    // precomputed gather offsets
__device__ __align__(16) float g_Y[NROWS * YCOLS];
__device__ __align__(16) float g_Hcat[NROWS * 2 * DIM];
__device__ __align__(16) float g_T[NROWS * DIM];
// bf16 hi/lo splits, row-major, k contiguous
__device__ __align__(16) __nv_bfloat16 g_Ah[NROWS * DIM];        // h1 split
__device__ __align__(16) __nv_bfloat16 g_Al[NROWS * DIM];
__device__ __align__(16) __nv_bfloat16 g_Hh[NROWS * 2 * DIM];    // Hcat split
__device__ __align__(16) __nv_bfloat16 g_Hl[NROWS * 2 * DIM];
__device__ __align__(16) __nv_bfloat16 g_Bh1[YCOLS * DIM];
__device__ __align__(16) __nv_bfloat16 g_Bl1[YCOLS * DIM];
__device__ __align__(16) __nv_bfloat16 g_Bh2[YCOLS * DIM];
__device__ __align__(16) __nv_bfloat16 g_Bl2[YCOLS * DIM];
__device__ __align__(16) __nv_bfloat16 g_Weh[DIM * 2 * DIM];     // we1 split [n=128][k=256]
__device__ __align__(16) __nv_bfloat16 g_Wel[DIM * 2 * DIM];

// ---------------- helpers ----------------------------------------------------
__device__ __forceinline__ void bf_split(float f, uint16_t& h, uint16_t& l) {
    __nv_bfloat16 bh = __float2bfloat16_rn(f);
    float r = f - __bfloat162float(bh);
    __nv_bfloat16 bl = __float2bfloat16_rn(r);
    h = *(uint16_t*)&bh;
    l = *(uint16_t*)&bl;
}
__device__ __forceinline__ void split_store4(char* hp, char* lp, float4 v) {
    uint16_t h0, h1, h2, h3, l0, l1, l2, l3;
    bf_split(v.x, h0, l0); bf_split(v.y, h1, l1);
    bf_split(v.z, h2, l2); bf_split(v.w, h3, l3);
    *(uint2*)hp = make_uint2((uint32_t)h0 | ((uint32_t)h1 << 16),
                             (uint32_t)h2 | ((uint32_t)h3 << 16));
    *(uint2*)lp = make_uint2((uint32_t)l0 | ((uint32_t)l1 << 16),
                             (uint32_t)l2 | ((uint32_t)l3 << 16));
}

// ------- kernel: prep x -> Hcat right half (fp32 + hi/lo split) --------------
__global__ void prep_kernel(const float* __restrict__ x) {
    int t = blockIdx.x * blockDim.x + threadIdx.x;    // over 6144*32
    if (t >= NROWS * 32) return;
    int i = t >> 5, q = t & 31;
    float4 v = ((const float4*)x)[t];
    size_t e = (size_t)i * 2 * DIM + DIM + q * 4;
    *(float4*)&g_Hcat[e] = v;
    split_store4((char*)g_Hh + e * 2, (char*)g_Hl + e * 2, v);
}

// ------ kernel: banded scores + softmax + precomputed gather offsets ---------
__global__ void attn_kernel(const float* __restrict__ x, const int* __restrict__ spk) {
    int warp = threadIdx.x >> 5;
    int lane = threadIdx.x & 31;
    int i = blockIdx.x * 4 + warp;
    if (i >= NROWS) return;

    float xi0 = x[i * DIM + lane];
    float xi1 = x[i * DIM + 32 + lane];
    float xi2 = x[i * DIM + 64 + lane];
    float xi3 = x[i * DIM + 96 + lane];

    float myscore = -3.4e38f;
    #pragma unroll
    for (int l = 0; l < BANDW; l++) {
        int j = i - WINSZ + l;
        if (j >= 0 && j < NROWS) {
            const float* xj = x + (size_t)j * DIM;
            float s = xi0 * xj[lane] + xi1 * xj[32 + lane]
                    + xi2 * xj[64 + lane] + xi3 * xj[96 + lane];
            #pragma unroll
            for (int off = 16; off; off >>= 1) s += __shfl_xor_sync(~0u, s, off);
            if (lane == l) myscore = s;
        }
    }
    int jl = i - WINSZ + lane;
    bool valid = (lane < BANDW) && (jl >= 0) && (jl < NROWS);
    float m = valid ? myscore : -3.4e38f;
    #pragma unroll
    for (int off = 16; off; off >>= 1) m = fmaxf(m, __shfl_xor_sync(~0u, m, off));
    m = fmaxf(m, 0.0f);
    float e = valid ? expf(myscore - m) : 0.0f;
    float sum = e;
    #pragma unroll
    for (int off = 16; off; off >>= 1) sum += __shfl_xor_sync(~0u, sum, off);
    int lo = max(0, i - WINSZ), hi = min(NROWS - 1, i + WINSZ);
    int nband = hi - lo + 1;
    float den = sum + (float)(NROWS - nband) * expf(-m);
    if (lane < BANDW) {
        g_attn[i * BANDW + lane] = valid ? (e / den) : 0.0f;
        int off = 0;
        if (valid) {
            bool same = (spk[jl] == spk[i]);
            bool pred = (lane >= WINSZ);
            int col = same ? (pred ? 0 : 1) : (pred ? 2 : 3);
            off = jl * YCOLS + col * DIM;
        }
        g_off[i * BANDW + lane] = off;
    }
}

// ------- kernel: pack layer weights -> bf16 hi/lo, layout [n(640)][k(128)] ---
__global__ void pack_kernel(const float* __restrict__ Wp1, const float* __restrict__ Ws1,
                            const float* __restrict__ Wsa1, const float* __restrict__ Wd1,
                            const float* __restrict__ Wag1,
                            const float* __restrict__ Wp2, const float* __restrict__ Ws2,
                            const float* __restrict__ Wsa2, const float* __restrict__ Wd2,
                            const float* __restrict__ Wag2) {
    int idx = blockIdx.x * blockDim.x + threadIdx.x;   // over 640*128
    if (idx >= YCOLS * DIM) return;
    int n = idx >> 7, k = idx & 127;
    int rel = n >> 7, d = n & 127;
    const float* s1;
    const float* s2;
    switch (rel) {
        case 0: s1 = Wp1;  s2 = Wp2;  break;
        case 1: s1 = Ws1;  s2 = Ws2;  break;
        case 2: s1 = Wsa1; s2 = Wsa2; break;
        case 3: s1 = Wd1;  s2 = Wd2;  break;
        default: s1 = Wag1; s2 = Wag2; break;
    }
    uint16_t h, l;
    bf_split(s1[k * DIM + d], h, l);
    *(uint16_t*)&g_Bh1[idx] = h;
    *(uint16_t*)&g_Bl1[idx] = l;
    bf_split(s2[k * DIM + d], h, l);
    *(uint16_t*)&g_Bh2[idx] = h;
    *(uint16_t*)&g_Bl2[idx] = l;
}

// ------- kernel: pack we1 [256][128] -> hi/lo blob [n=128][k=256] ------------
__global__ void packE_kernel(const float* __restrict__ we1) {
    int idx = blockIdx.x * blockDim.x + threadIdx.x;   // over 128*256
    if (idx >= DIM * 2 * DIM) return;
    int n = idx >> 8, k = idx & 255;
    uint16_t h, l;
    bf_split(we1[k * DIM + n], h, l);
    *(uint16_t*)&g_Weh[idx] = h;
    *(uint16_t*)&g_Wel[idx] = l;
}

// ------- kernel: wmma bf16-split GEMM  C[M x ...] = A @ B^T ------------------
template <int KCHUNKS, bool EPI>
__global__ void __launch_bounds__(256, 2)
wgemm_kernel(const __nv_bfloat16* __restrict__ Ah, const __nv_bfloat16* __restrict__ Al,
             int lda4,
             const __nv_bfloat16* __restrict__ Bh, const __nv_bfloat16* __restrict__ Bl,
             int ldb4,
             float* __restrict__ C, int ldc, const float* __restrict__ bias) {
    extern __shared__ __nv_bfloat16 sm[];
    __nv_bfloat16* Ah_s = sm;                               // 128 x 136
    __nv_bfloat16* Al_s = Ah_s + 128 * LDS_PAD;
    __nv_bfloat16* Bh_s = Al_s + 128 * LDS_PAD;             // 64 x 136
    __nv_bfloat16* Bl_s = Bh_s + 64 * LDS_PAD;

    int tid = threadIdx.x;
    int ntile = blockIdx.x, mtile = blockIdx.y;
    int warp = tid >> 5, lane = tid & 31;
    int wm = warp & 3;            // m offset = wm*32
    int wn = warp >> 2;           // n offset = wn*32

    wmma::fragment<wmma::accumulator, 16, 16, 16, float> acc[2][2];
    #pragma unroll
    for (int u = 0; u < 2; u++)
        #pragma unroll
        for (int v = 0; v < 2; v++) wmma::fill_fragment(acc[u][v], 0.0f);

    const float4* ga_h = (const float4*)Ah;
    const float4* ga_l = (const float4*)Al;
    const float4* gb_h = (const float4*)Bh;
    const float4* gb_l = (const float4*)Bl;

    #pragma unroll
    for (int kc = 0; kc < KCHUNKS; kc++) {
        if (kc) __syncthreads();
        #pragma unroll
        for (int it = 0; it < 8; it++) {                    // A pair: 128x16 float4
            int v = tid + it * 256;
            int row = v >> 4, q = v & 15;
            int gi = (mtile * MT + row) * lda4 + kc * 16 + q;
            *(float4*)&Ah_s[row * LDS_PAD + q * 8] = ga_h[gi];
            *(float4*)&Al_s[row * LDS_PAD + q * 8] = ga_l[gi];
        }
        #pragma unroll
        for (int it = 0; it < 4; it++) {                    // B pair: 64x16 float4
            int v = tid + it * 256;
            int row = v >> 4, q = v & 15;
            int gi = (ntile * NT + row) * ldb4 + kc * 16 + q;
            *(float4*)&Bh_s[row * LDS_PAD + q * 8] = gb_h[gi];
            *(float4*)&Bl_s[row * LDS_PAD + q * 8] = gb_l[gi];
        }
        __syncthreads();

        #pragma unroll
        for (int ks = 0; ks < 8; ks++) {
            wmma::fragment<wmma::matrix_a, 16, 16, 16, __nv_bfloat16, wmma::row_major> ah[2], al[2];
            wmma::fragment<wmma::matrix_b, 16, 16, 16, __nv_bfloat16, wmma::col_major> bh[2], bl[2];
            #pragma unroll
            for (int u = 0; u < 2; u++) {
                int r = wm * 32 + u * 16;
                wmma::load_matrix_sync(ah[u], &Ah_s[r * LDS_PAD + ks * 16], LDS_PAD);
                wmma::load_matrix_sync(al[u], &Al_s[r * LDS_PAD + ks * 16], LDS_PAD);
            }
            #pragma unroll
            for (int v = 0; v < 2; v++) {
                int r = wn * 32 + v * 16;
                wmma::load_matrix_sync(bh[v], &Bh_s[r * LDS_PAD + ks * 16], LDS_PAD);
                wmma::load_matrix_sync(bl[v], &Bl_s[r * LDS_PAD + ks * 16], LDS_PAD);
            }
            #pragma unroll
            for (int u = 0; u < 2; u++)
                #pragma unroll
                for (int v = 0; v < 2; v++) {
                    wmma::mma_sync(acc[u][v], ah[u], bh[v], acc[u][v]);
                    wmma::mma_sync(acc[u][v], ah[u], bl[v], acc[u][v]);
                    wmma::mma_sync(acc[u][v], al[u], bh[v], acc[u][v]);
                }
        }
    }

    if (!EPI) {
        #pragma unroll
        for (int u = 0; u < 2; u++)
            #pragma unroll
            for (int v = 0; v < 2; v++) {
                int row = mtile * MT + wm * 32 + u * 16;
                int col = ntile * NT + wn * 32 + v * 16;
                wmma::store_matrix_sync(&C[(size_t)row * ldc + col], acc[u][v],
                                        ldc, wmma::mem_row_major);
            }
    } else {
        __syncthreads();
        float* stage = (float*)sm + warp * 1024;
        #pragma unroll
        for (int u = 0; u < 2; u++)
            #pragma unroll
            for (int v = 0; v < 2; v++)
                wmma::store_matrix_sync(&stage[u * 16 * 32 + v * 16], acc[u][v],
                                        32, wmma::mem_row_major);
        int row = mtile * MT + wm * 32 + lane;
        int colbase = ntile * NT + wn * 32;
        #pragma unroll
        for (int c = 0; c < 32; c += 4) {
            float4 val = *(float4*)&stage[lane * 32 + c];
            float4 bv = *(const float4*)&bias[colbase + c];
            val.x = fmaxf(val.x + bv.x, 0.0f);
            val.y = fmaxf(val.y + bv.y, 0.0f);
            val.z = fmaxf(val.z + bv.z, 0.0f);
            val.w = fmaxf(val.w + bv.w, 0.0f);
            *(float4*)&C[(size_t)row * ldc + colbase + c] = val;
        }
    }
}

// ------- kernel: banded combine + aggr + relu (warp/row, broadcast a/off) ----
// MODE 0: write bf16 hi/lo A (h1). MODE 1: write Hcat left half fp32 + split.
template <int MODE>
__global__ void combine_kernel() {
    int warp = threadIdx.x >> 5, lane = threadIdx.x & 31;
    int i = blockIdx.x * 8 + warp;
    if (i >= NROWS) return;

    const float* arow = g_attn + i * BANDW;
    const int* orow = g_off + i * BANDW;
    const float4* Yv = (const float4*)g_Y;

    float da = arow[WINSZ];
    float4 yv = Yv[(i * YCOLS + 4 * DIM) / 4 + lane];
    float4 acc = make_float4(da * yv.x, da * yv.y, da * yv.z, da * yv.w);

    #pragma unroll
    for (int l = 0; l < BANDW; l++) {
        float a = arow[l];            // broadcast (same addr across warp)
        int off = orow[l];            // broadcast
        float4 y = Yv[off / 4 + lane];
        acc.x += a * y.x; acc.y += a * y.y;
        acc.z += a * y.z; acc.w += a * y.w;
    }
    acc.x = fmaxf(acc.x, 0.0f); acc.y = fmaxf(acc.y, 0.0f);
    acc.z = fmaxf(acc.z, 0.0f); acc.w = fmaxf(acc.w, 0.0f);

    if (MODE == 0) {
        size_t e = (size_t)i * DIM + lane * 4;
        split_store4((char*)g_Ah + e * 2, (char*)g_Al + e * 2, acc);
    } else {
        size_t e = (size_t)i * 2 * DIM + lane * 4;
        *(float4*)&g_Hcat[e] = acc;
        split_store4((char*)g_Hh + e * 2, (char*)g_Hl + e * 2, acc);
    }
}

// ---------------- kernel: emotion / sentiment heads --------------------------
__global__ void head_kernel(const float* __restrict__ we2, const float* __restrict__ be2,
                            const float* __restrict__ ws, const float* __restrict__ bs,
                            float* __restrict__ out) {
    int warp = threadIdx.x >> 5, lane = threadIdx.x & 31;
    int i = blockIdx.x * 8 + warp;
    if (i >= NROWS) return;

    float tv[4];
    #pragma unroll
    for (int c = 0; c < 4; c++) tv[c] = g_T[i * DIM + c * 32 + lane];
    float hv[8];
    #pragma unroll
    for (int c = 0; c < 8; c++) hv[c] = g_Hcat[i * 2 * DIM + c * 32 + lane];

    #pragma unroll
    for (int e = 0; e < NEMO; e++) {
        float s = 0.0f;
        #pragma unroll
        for (int c = 0; c < 4; c++) s += tv[c] * we2[(c * 32 + lane) * NEMO + e];
        #pragma unroll
        for (int off = 16; off; off >>= 1) s += __shfl_xor_sync(~0u, s, off);

        float s2 = 0.0f;
        #pragma unroll
        for (int c = 0; c < 8; c++) s2 += hv[c] * ws[(c * 32 + lane) * NEMO + e];
        #pragma unroll
        for (int off = 16; off; off >>= 1) s2 += __shfl_xor_sync(~0u, s2, off);

        if (lane == 0) {
            out[i * NEMO + e] = s + be2[e];
            out[NROWS * NEMO + i * NEMO + e] = s2 + bs[e];
        }
    }
}

// -----------------------------------------------------------------------------
extern "C" void kernel_launch(void* const* d_in, const int* in_sizes, int n_in,
                              void* d_out, int out_size) {
    const float* x       = (const float*)d_in[0];
    const int*   spk     = (const int*)d_in[1];
    const float* Wp1     = (const float*)d_in[2];
    const float* Ws1     = (const float*)d_in[3];
    const float* Wsa1    = (const float*)d_in[4];
    const float* Wd1     = (const float*)d_in[5];
    const float* Wp2     = (const float*)d_in[6];
    const float* Ws2     = (const float*)d_in[7];
    const float* Wsa2    = (const float*)d_in[8];
    const float* Wd2     = (const float*)d_in[9];
    const float* Wag1    = (const float*)d_in[10];
    const float* Wag2    = (const float*)d_in[11];
    const float* we1     = (const float*)d_in[12];
    const float* be1     = (const float*)d_in[13];
    const float* we2     = (const float*)d_in[14];
    const float* be2     = (const float*)d_in[15];
    const float* wsw     = (const float*)d_in[16];
    const float* bsb     = (const float*)d_in[17];
    float* out = (float*)d_out;

    cudaFuncSetAttribute(wgemm_kernel<1, false>,
                         cudaFuncAttributeMaxDynamicSharedMemorySize, WG_SMEM);
    cudaFuncSetAttribute(wgemm_kernel<2, true>,
                         cudaFuncAttributeMaxDynamicSharedMemorySize, WG_SMEM);

    __nv_bfloat16 *ah, *al, *hh, *hl, *bh1, *bl1, *bh2, *bl2, *weh, *wel;
    float *yp, *tp;
    cudaGetSymbolAddress((void**)&ah, g_Ah);
    cudaGetSymbolAddress((void**)&al, g_Al);
    cudaGetSymbolAddress((void**)&hh, g_Hh);
    cudaGetSymbolAddress((void**)&hl, g_Hl);
    cudaGetSymbolAddress((void**)&bh1, g_Bh1);
    cudaGetSymbolAddress((void**)&bl1, g_Bl1);
    cudaGetSymbolAddress((void**)&bh2, g_Bh2);
    cudaGetSymbolAddress((void**)&bl2, g_Bl2);
    cudaGetSymbolAddress((void**)&weh, g_Weh);
    cudaGetSymbolAddress((void**)&wel, g_Wel);
    cudaGetSymbolAddress((void**)&yp, g_Y);
    cudaGetSymbolAddress((void**)&tp, g_T);

    prep_kernel<<<(NROWS * 32 + 255) / 256, 256>>>(x);
    attn_kernel<<<NROWS / 4, 128>>>(x, spk);
    pack_kernel<<<(YCOLS * DIM + 255) / 256, 256>>>(Wp1, Ws1, Wsa1, Wd1, Wag1,
                                                    Wp2, Ws2, Wsa2, Wd2, Wag2);
    packE_kernel<<<(DIM * 2 * DIM + 255) / 256, 256>>>(we1);
    // Y = x @ Wcat1   (A = right half of Hcat split, lda = 256)
    wgemm_kernel<1, false><<<dim3(NTILES, MTILES), 256, WG_SMEM>>>(
        hh + DIM, hl + DIM, 32, bh1, bl1, 16, yp, YCOLS, nullptr);
    combine_kernel<0><<<NROWS / 8, 256>>>();      // -> g_Ah/g_Al (h1)
    // Y = h1 @ Wcat2
    wgemm_kernel<1, false><<<dim3(NTILES, MTILES), 256, WG_SMEM>>>(
        ah, al, 16, bh2, bl2, 16, yp, YCOLS, nullptr);
    combine_kernel<1><<<NROWS / 8, 256>>>();      // -> Hcat left + split
    // T = relu(Hcat @ we1 + be1)   (K = 256 -> 2 chunks)
    wgemm_kernel<2, true><<<dim3(2, MTILES), 256, WG_SMEM>>>(
        hh, hl, 32, weh, wel, 32, tp, DIM, be1);
    head_kernel<<<NROWS / 8, 256>>>(we2, be2, wsw, bsb, out);
}

// round 12
// speedup vs baseline: 1.5076x; 1.0316x over previous
#include <cuda_runtime.h>
#include <cuda_bf16.h>
#include <mma.h>
#include <math.h>
#include <stdint.h>

using namespace nvcuda;

#define NROWS 6144
#define DIM 128
#define WINSZ 10
#define BANDW 21
#define NEMO 7
#define YCOLS 640        // [W_pred | W_suc | W_same | W_diff | w_aggr] * 128
#define MT 128           // GEMM M tile
#define NT 64            // GEMM N tile
#define MTILES 48        // 6144/128
#define NTILES 10        // 640/64
#define LDS_PAD 136      // smem row stride in bf16 elems (128 + 8)

// dynamic smem: Ah(128) + Al(128) + Bh(64) + Bl(64) rows * 136 * 2B
#define WG_SMEM ((128 + 128 + 64 + 64) * LDS_PAD * 2)

// setup kernel block ranges (256 threads each)
#define SB_ATTN 768          // 6144 rows / 8 warps
#define SB_PREP 768          // 6144*32 float4 / 256
#define SB_PACK 320          // 640*128 / 256
#define SB_PACKE 128         // 128*256 / 256
#define SB_TOTAL (SB_ATTN + SB_PREP + SB_PACK + SB_PACKE)

// ---------------- scratch (device globals; no allocation allowed) ------------
__device__ __align__(16) float g_attn[NROWS * BANDW];
__device__ __align__(16) int   g_off[NROWS * BANDW];    // precomputed gather offsets
__device__ __align__(16) float g_Y[NROWS * YCOLS];
__device__ __align__(16) float g_Hcat[NROWS * 2 * DIM];
__device__ __align__(16) float g_T[NROWS * DIM];
// bf16 hi/lo splits, row-major, k contiguous
__device__ __align__(16) __nv_bfloat16 g_Ah[NROWS * DIM];        // h1 split
__device__ __align__(16) __nv_bfloat16 g_Al[NROWS * DIM];
__device__ __align__(16) __nv_bfloat16 g_Hh[NROWS * 2 * DIM];    // Hcat split
__device__ __align__(16) __nv_bfloat16 g_Hl[NROWS * 2 * DIM];
__device__ __align__(16) __nv_bfloat16 g_Bh1[YCOLS * DIM];
__device__ __align__(16) __nv_bfloat16 g_Bl1[YCOLS * DIM];
__device__ __align__(16) __nv_bfloat16 g_Bh2[YCOLS * DIM];
__device__ __align__(16) __nv_bfloat16 g_Bl2[YCOLS * DIM];
__device__ __align__(16) __nv_bfloat16 g_Weh[DIM * 2 * DIM];     // we1 split [n=128][k=256]
__device__ __align__(16) __nv_bfloat16 g_Wel[DIM * 2 * DIM];

// ---------------- helpers ----------------------------------------------------
__device__ __forceinline__ void bf_split(float f, uint16_t& h, uint16_t& l) {
    __nv_bfloat16 bh = __float2bfloat16_rn(f);
    float r = f - __bfloat162float(bh);
    __nv_bfloat16 bl = __float2bfloat16_rn(r);
    h = *(uint16_t*)&bh;
    l = *(uint16_t*)&bl;
}
__device__ __forceinline__ void split_store4(char* hp, char* lp, float4 v) {
    uint16_t h0, h1, h2, h3, l0, l1, l2, l3;
    bf_split(v.x, h0, l0); bf_split(v.y, h1, l1);
    bf_split(v.z, h2, l2); bf_split(v.w, h3, l3);
    *(uint2*)hp = make_uint2((uint32_t)h0 | ((uint32_t)h1 << 16),
                             (uint32_t)h2 | ((uint32_t)h3 << 16));
    *(uint2*)lp = make_uint2((uint32_t)l0 | ((uint32_t)l1 << 16),
                             (uint32_t)l2 | ((uint32_t)l3 << 16));
}

// ------- kernel: fused setup (attn + prep + pack + packE), block-ranged ------
__global__ void __launch_bounds__(256)
setup_kernel(const float* __restrict__ x, const int* __restrict__ spk,
             const float* __restrict__ Wp1, const float* __restrict__ Ws1,
             const float* __restrict__ Wsa1, const float* __restrict__ Wd1,
             const float* __restrict__ Wag1,
             const float* __restrict__ Wp2, const float* __restrict__ Ws2,
             const float* __restrict__ Wsa2, const float* __restrict__ Wd2,
             const float* __restrict__ Wag2,
             const float* __restrict__ we1) {
    int blk = blockIdx.x;
    int tid = threadIdx.x;

    if (blk < SB_ATTN) {
        // ---- banded scores + softmax + gather offsets (warp per row) ----
        int warp = tid >> 5, lane = tid & 31;
        int i = blk * 8 + warp;

        float xi0 = x[i * DIM + lane];
        float xi1 = x[i * DIM + 32 + lane];
        float xi2 = x[i * DIM + 64 + lane];
        float xi3 = x[i * DIM + 96 + lane];

        float myscore = -3.4e38f;
        #pragma unroll
        for (int l = 0; l < BANDW; l++) {
            int j = i - WINSZ + l;
            if (j >= 0 && j < NROWS) {
                const float* xj = x + (size_t)j * DIM;
                float s = xi0 * xj[lane] + xi1 * xj[32 + lane]
                        + xi2 * xj[64 + lane] + xi3 * xj[96 + lane];
                #pragma unroll
                for (int off = 16; off; off >>= 1) s += __shfl_xor_sync(~0u, s, off);
                if (lane == l) myscore = s;
            }
        }
        int jl = i - WINSZ + lane;
        bool valid = (lane < BANDW) && (jl >= 0) && (jl < NROWS);
        float m = valid ? myscore : -3.4e38f;
        #pragma unroll
        for (int off = 16; off; off >>= 1) m = fmaxf(m, __shfl_xor_sync(~0u, m, off));
        m = fmaxf(m, 0.0f);
        float e = valid ? expf(myscore - m) : 0.0f;
        float sum = e;
        #pragma unroll
        for (int off = 16; off; off >>= 1) sum += __shfl_xor_sync(~0u, sum, off);
        int lo = max(0, i - WINSZ), hi = min(NROWS - 1, i + WINSZ);
        int nband = hi - lo + 1;
        float den = sum + (float)(NROWS - nband) * expf(-m);
        if (lane < BANDW) {
            g_attn[i * BANDW + lane] = valid ? (e / den) : 0.0f;
            int off = 0;
            if (valid) {
                bool same = (spk[jl] == spk[i]);
                bool pred = (lane >= WINSZ);
                int col = same ? (pred ? 0 : 1) : (pred ? 2 : 3);
                off = jl * YCOLS + col * DIM;
            }
            g_off[i * BANDW + lane] = off;
        }
    } else if (blk < SB_ATTN + SB_PREP) {
        // ---- prep: x -> Hcat right half fp32 + bf16 hi/lo split ----
        int t = (blk - SB_ATTN) * 256 + tid;          // over 6144*32 float4
        int i = t >> 5, q = t & 31;
        float4 v = ((const float4*)x)[t];
        size_t e = (size_t)i * 2 * DIM + DIM + q * 4;
        *(float4*)&g_Hcat[e] = v;
        split_store4((char*)g_Hh + e * 2, (char*)g_Hl + e * 2, v);
    } else if (blk < SB_ATTN + SB_PREP + SB_PACK) {
        // ---- pack layer weights -> [n(640)][k(128)] hi/lo ----
        int idx = (blk - SB_ATTN - SB_PREP) * 256 + tid;   // over 640*128
        int n = idx >> 7, k = idx & 127;
        int rel = n >> 7, d = n & 127;
        const float* s1;
        const float* s2;
        switch (rel) {
            case 0: s1 = Wp1;  s2 = Wp2;  break;
            case 1: s1 = Ws1;  s2 = Ws2;  break;
            case 2: s1 = Wsa1; s2 = Wsa2; break;
            case 3: s1 = Wd1;  s2 = Wd2;  break;
            default: s1 = Wag1; s2 = Wag2; break;
        }
        uint16_t h, l;
        bf_split(s1[k * DIM + d], h, l);
        *(uint16_t*)&g_Bh1[idx] = h;
        *(uint16_t*)&g_Bl1[idx] = l;
        bf_split(s2[k * DIM + d], h, l);
        *(uint16_t*)&g_Bh2[idx] = h;
        *(uint16_t*)&g_Bl2[idx] = l;
    } else {
        // ---- pack we1 [256][128] -> hi/lo [n=128][k=256] ----
        int idx = (blk - SB_ATTN - SB_PREP - SB_PACK) * 256 + tid;  // over 128*256
        int n = idx >> 8, k = idx & 255;
        uint16_t h, l;
        bf_split(we1[k * DIM + n], h, l);
        *(uint16_t*)&g_Weh[idx] = h;
        *(uint16_t*)&g_Wel[idx] = l;
    }
}

// ------- kernel: wmma bf16-split GEMM  C[M x ...] = A @ B^T ------------------
template <int KCHUNKS, bool EPI>
__global__ void __launch_bounds__(256, 2)
wgemm_kernel(const __nv_bfloat16* __restrict__ Ah, const __nv_bfloat16* __restrict__ Al,
             int lda4,
             const __nv_bfloat16* __restrict__ Bh, const __nv_bfloat16* __restrict__ Bl,
             int ldb4,
             float* __restrict__ C, int ldc, const float* __restrict__ bias) {
    extern __shared__ __nv_bfloat16 sm[];
    __nv_bfloat16* Ah_s = sm;                               // 128 x 136
    __nv_bfloat16* Al_s = Ah_s + 128 * LDS_PAD;
    __nv_bfloat16* Bh_s = Al_s + 128 * LDS_PAD;             // 64 x 136
    __nv_bfloat16* Bl_s = Bh_s + 64 * LDS_PAD;

    int tid = threadIdx.x;
    int ntile = blockIdx.x, mtile = blockIdx.y;
    int warp = tid >> 5, lane = tid & 31;
    int wm = warp & 3;            // m offset = wm*32
    int wn = warp >> 2;           // n offset = wn*32

    wmma::fragment<wmma::accumulator, 16, 16, 16, float> acc[2][2];
    #pragma unroll
    for (int u = 0; u < 2; u++)
        #pragma unroll
        for (int v = 0; v < 2; v++) wmma::fill_fragment(acc[u][v], 0.0f);

    const float4* ga_h = (const float4*)Ah;
    const float4* ga_l = (const float4*)Al;
    const float4* gb_h = (const float4*)Bh;
    const float4* gb_l = (const float4*)Bl;

    #pragma unroll
    for (int kc = 0; kc < KCHUNKS; kc++) {
        if (kc) __syncthreads();
        #pragma unroll
        for (int it = 0; it < 8; it++) {                    // A pair: 128x16 float4
            int v = tid + it * 256;
            int row = v >> 4, q = v & 15;
            int gi = (mtile * MT + row) * lda4 + kc * 16 + q;
            *(float4*)&Ah_s[row * LDS_PAD + q * 8] = ga_h[gi];
            *(float4*)&Al_s[row * LDS_PAD + q * 8] = ga_l[gi];
        }
        #pragma unroll
        for (int it = 0; it < 4; it++) {                    // B pair: 64x16 float4
            int v = tid + it * 256;
            int row = v >> 4, q = v & 15;
            int gi = (ntile * NT + row) * ldb4 + kc * 16 + q;
            *(float4*)&Bh_s[row * LDS_PAD + q * 8] = gb_h[gi];
            *(float4*)&Bl_s[row * LDS_PAD + q * 8] = gb_l[gi];
        }
        __syncthreads();

        #pragma unroll
        for (int ks = 0; ks < 8; ks++) {
            wmma::fragment<wmma::matrix_a, 16, 16, 16, __nv_bfloat16, wmma::row_major> ah[2], al[2];
            wmma::fragment<wmma::matrix_b, 16, 16, 16, __nv_bfloat16, wmma::col_major> bh[2], bl[2];
            #pragma unroll
            for (int u = 0; u < 2; u++) {
                int r = wm * 32 + u * 16;
                wmma::load_matrix_sync(ah[u], &Ah_s[r * LDS_PAD + ks * 16], LDS_PAD);
                wmma::load_matrix_sync(al[u], &Al_s[r * LDS_PAD + ks * 16], LDS_PAD);
            }
            #pragma unroll
            for (int v = 0; v < 2; v++) {
                int r = wn * 32 + v * 16;
                wmma::load_matrix_sync(bh[v], &Bh_s[r * LDS_PAD + ks * 16], LDS_PAD);
                wmma::load_matrix_sync(bl[v], &Bl_s[r * LDS_PAD + ks * 16], LDS_PAD);
            }
            #pragma unroll
            for (int u = 0; u < 2; u++)
                #pragma unroll
                for (int v = 0; v < 2; v++) {
                    wmma::mma_sync(acc[u][v], ah[u], bh[v], acc[u][v]);
                    wmma::mma_sync(acc[u][v], ah[u], bl[v], acc[u][v]);
                    wmma::mma_sync(acc[u][v], al[u], bh[v], acc[u][v]);
                }
        }
    }

    if (!EPI) {
        #pragma unroll
        for (int u = 0; u < 2; u++)
            #pragma unroll
            for (int v = 0; v < 2; v++) {
                int row = mtile * MT + wm * 32 + u * 16;
                int col = ntile * NT + wn * 32 + v * 16;
                wmma::store_matrix_sync(&C[(size_t)row * ldc + col], acc[u][v],
                                        ldc, wmma::mem_row_major);
            }
    } else {
        __syncthreads();
        float* stage = (float*)sm + warp * 1024;
        #pragma unroll
        for (int u = 0; u < 2; u++)
            #pragma unroll
            for (int v = 0; v < 2; v++)
                wmma::store_matrix_sync(&stage[u * 16 * 32 + v * 16], acc[u][v],
                                        32, wmma::mem_row_major);
        int row = mtile * MT + wm * 32 + lane;
        int colbase = ntile * NT + wn * 32;
        #pragma unroll
        for (int c = 0; c < 32; c += 4) {
            float4 val = *(float4*)&stage[lane * 32 + c];
            float4 bv = *(const float4*)&bias[colbase + c];
            val.x = fmaxf(val.x + bv.x, 0.0f);
            val.y = fmaxf(val.y + bv.y, 0.0f);
            val.z = fmaxf(val.z + bv.z, 0.0f);
            val.w = fmaxf(val.w + bv.w, 0.0f);
            *(float4*)&C[(size_t)row * ldc + colbase + c] = val;
        }
    }
}

// ------- kernel: banded combine + aggr + relu (warp/row, broadcast a/off) ----
// MODE 0: write bf16 hi/lo A (h1). MODE 1: write Hcat left half fp32 + split.
template <int MODE>
__global__ void combine_kernel() {
    int warp = threadIdx.x >> 5, lane = threadIdx.x & 31;
    int i = blockIdx.x * 8 + warp;
    if (i >= NROWS) return;

    const float* arow = g_attn + i * BANDW;
    const int* orow = g_off + i * BANDW;
    const float4* Yv = (const float4*)g_Y;

    float da = arow[WINSZ];
    float4 yv = Yv[(i * YCOLS + 4 * DIM) / 4 + lane];
    float4 acc = make_float4(da * yv.x, da * yv.y, da * yv.z, da * yv.w);

    #pragma unroll
    for (int l = 0; l < BANDW; l++) {
        float a = arow[l];            // broadcast (same addr across warp)
        int off = orow[l];            // broadcast
        float4 y = Yv[off / 4 + lane];
        acc.x += a * y.x; acc.y += a * y.y;
        acc.z += a * y.z; acc.w += a * y.w;
    }
    acc.x = fmaxf(acc.x, 0.0f); acc.y = fmaxf(acc.y, 0.0f);
    acc.z = fmaxf(acc.z, 0.0f); acc.w = fmaxf(acc.w, 0.0f);

    if (MODE == 0) {
        size_t e = (size_t)i * DIM + lane * 4;
        split_store4((char*)g_Ah + e * 2, (char*)g_Al + e * 2, acc);
    } else {
        size_t e = (size_t)i * 2 * DIM + lane * 4;
        *(float4*)&g_Hcat[e] = acc;
        split_store4((char*)g_Hh + e * 2, (char*)g_Hl + e * 2, acc);
    }
}

// ---------------- kernel: emotion / sentiment heads --------------------------
__global__ void head_kernel(const float* __restrict__ we2, const float* __restrict__ be2,
                            const float* __restrict__ ws, const float* __restrict__ bs,
                            float* __restrict__ out) {
    int warp = threadIdx.x >> 5, lane = threadIdx.x & 31;
    int i = blockIdx.x * 8 + warp;
    if (i >= NROWS) return;

    float tv[4];
    #pragma unroll
    for (int c = 0; c < 4; c++) tv[c] = g_T[i * DIM + c * 32 + lane];
    float hv[8];
    #pragma unroll
    for (int c = 0; c < 8; c++) hv[c] = g_Hcat[i * 2 * DIM + c * 32 + lane];

    #pragma unroll
    for (int e = 0; e < NEMO; e++) {
        float s = 0.0f;
        #pragma unroll
        for (int c = 0; c < 4; c++) s += tv[c] * we2[(c * 32 + lane) * NEMO + e];
        #pragma unroll
        for (int off = 16; off; off >>= 1) s += __shfl_xor_sync(~0u, s, off);

        float s2 = 0.0f;
        #pragma unroll
        for (int c = 0; c < 8; c++) s2 += hv[c] * ws[(c * 32 + lane) * NEMO + e];
        #pragma unroll
        for (int off = 16; off; off >>= 1) s2 += __shfl_xor_sync(~0u, s2, off);

        if (lane == 0) {
            out[i * NEMO + e] = s + be2[e];
            out[NROWS * NEMO + i * NEMO + e] = s2 + bs[e];
        }
    }
}

// -----------------------------------------------------------------------------
extern "C" void kernel_launch(void* const* d_in, const int* in_sizes, int n_in,
                              void* d_out, int out_size) {
    const float* x       = (const float*)d_in[0];
    const int*   spk     = (const int*)d_in[1];
    const float* Wp1     = (const float*)d_in[2];
    const float* Ws1     = (const float*)d_in[3];
    const float* Wsa1    = (const float*)d_in[4];
    const float* Wd1     = (const float*)d_in[5];
    const float* Wp2     = (const float*)d_in[6];
    const float* Ws2     = (const float*)d_in[7];
    const float* Wsa2    = (const float*)d_in[8];
    const float* Wd2     = (const float*)d_in[9];
    const float* Wag1    = (const float*)d_in[10];
    const float* Wag2    = (const float*)d_in[11];
    const float* we1     = (const float*)d_in[12];
    const float* be1     = (const float*)d_in[13];
    const float* we2     = (const float*)d_in[14];
    const float* be2     = (const float*)d_in[15];
    const float* wsw     = (const float*)d_in[16];
    const float* bsb     = (const float*)d_in[17];
    float* out = (float*)d_out;

    cudaFuncSetAttribute(wgemm_kernel<1, false>,
                         cudaFuncAttributeMaxDynamicSharedMemorySize, WG_SMEM);
    cudaFuncSetAttribute(wgemm_kernel<2, true>,
                         cudaFuncAttributeMaxDynamicSharedMemorySize, WG_SMEM);

    __nv_bfloat16 *ah, *al, *hh, *hl, *bh1, *bl1, *bh2, *bl2, *weh, *wel;
    float *yp, *tp;
    cudaGetSymbolAddress((void**)&ah, g_Ah);
    cudaGetSymbolAddress((void**)&al, g_Al);
    cudaGetSymbolAddress((void**)&hh, g_Hh);
    cudaGetSymbolAddress((void**)&hl, g_Hl);
    cudaGetSymbolAddress((void**)&bh1, g_Bh1);
    cudaGetSymbolAddress((void**)&bl1, g_Bl1);
    cudaGetSymbolAddress((void**)&bh2, g_Bh2);
    cudaGetSymbolAddress((void**)&bl2, g_Bl2);
    cudaGetSymbolAddress((void**)&weh, g_Weh);
    cudaGetSymbolAddress((void**)&wel, g_Wel);
    cudaGetSymbolAddress((void**)&yp, g_Y);
    cudaGetSymbolAddress((void**)&tp, g_T);

    // 1. fused setup: attn + prep + pack + packE (all independent)
    setup_kernel<<<SB_TOTAL, 256>>>(x, spk, Wp1, Ws1, Wsa1, Wd1, Wag1,
                                    Wp2, Ws2, Wsa2, Wd2, Wag2, we1);
    // 2. Y = x @ Wcat1   (A = right half of Hcat split, lda = 256 elems = 32 float4)
    wgemm_kernel<1, false><<<dim3(NTILES, MTILES), 256, WG_SMEM>>>(
        hh + DIM, hl + DIM, 32, bh1, bl1, 16, yp, YCOLS, nullptr);
    // 3. h1 = band-combine -> bf16 hi/lo
    combine_kernel<0><<<NROWS / 8, 256>>>();
    // 4. Y = h1 @ Wcat2
    wgemm_kernel<1, false><<<dim3(NTILES, MTILES), 256, WG_SMEM>>>(
        ah, al, 16, bh2, bl2, 16, yp, YCOLS, nullptr);
    // 5. h2 = band-combine -> Hcat left half + split
    combine_kernel<1><<<NROWS / 8, 256>>>();
    // 6. T = relu(Hcat @ we1 + be1)   (K = 256 -> 2 chunks)
    wgemm_kernel<2, true><<<dim3(2, MTILES), 256, WG_SMEM>>>(
        hh, hl, 32, weh, wel, 32, tp, DIM, be1);
    // 7. heads
    head_kernel<<<NROWS / 8, 256>>>(we2, be2, wsw, bsb, out);
}

// round 14
// speedup vs baseline: 1.6649x; 1.1044x over previous
#include <cuda_runtime.h>
#include <cuda_bf16.h>
#include <mma.h>
#include <math.h>
#include <stdint.h>

using namespace nvcuda;

#define NROWS 6144
#define DIM 128
#define WINSZ 10
#define BANDW 21
#define NEMO 7
#define YCOLS 640        // [W_pred | W_suc | W_same | W_diff | w_aggr] * 128
#define MT 128           // GEMM M tile
#define NT 64            // GEMM N tile
#define MTILES 48        // 6144/128
#define NTILES 10        // 640/64
#define LP 72            // smem row stride (bf16) for 64-elem k-chunk; 144B = 16B-aligned

// per-stage smem (bf16 elems): Ah 128*72=9216, Al 9216, Bh 64*72=4608, Bl 4608
#define ST_AH 0
#define ST_AL 9216
#define ST_BH 18432
#define ST_BL 23040
#define ST_ELEMS 27648           // per stage
#define WG_SMEM (2 * ST_ELEMS * 2)   // 110592 bytes

// setup kernel block ranges (256 threads each)
#define SB_ATTN 768          // 6144 rows / 8 warps
#define SB_PREP 768          // 6144*32 float4 / 256
#define SB_PACK 320          // 640*128 / 256
#define SB_PACKE 128         // 128*256 / 256
#define SB_TOTAL (SB_ATTN + SB_PREP + SB_PACK + SB_PACKE)

// ---------------- scratch (device globals; no allocation allowed) ------------
__device__ __align__(16) float g_attn[NROWS * BANDW];
__device__ __align__(16) int   g_off[NROWS * BANDW];
__device__ __align__(16) float g_Y[NROWS * YCOLS];
__device__ __align__(16) float g_Hcat[NROWS * 2 * DIM];
__device__ __align__(16) float g_T[NROWS * DIM];
__device__ __align__(16) __nv_bfloat16 g_Ah[NROWS * DIM];
__device__ __align__(16) __nv_bfloat16 g_Al[NROWS * DIM];
__device__ __align__(16) __nv_bfloat16 g_Hh[NROWS * 2 * DIM];
__device__ __align__(16) __nv_bfloat16 g_Hl[NROWS * 2 * DIM];
__device__ __align__(16) __nv_bfloat16 g_Bh1[YCOLS * DIM];
__device__ __align__(16) __nv_bfloat16 g_Bl1[YCOLS * DIM];
__device__ __align__(16) __nv_bfloat16 g_Bh2[YCOLS * DIM];
__device__ __align__(16) __nv_bfloat16 g_Bl2[YCOLS * DIM];
__device__ __align__(16) __nv_bfloat16 g_Weh[DIM * 2 * DIM];
__device__ __align__(16) __nv_bfloat16 g_Wel[DIM * 2 * DIM];

// ---------------- helpers ----------------------------------------------------
__device__ __forceinline__ void bf_split(float f, uint16_t& h, uint16_t& l) {
    __nv_bfloat16 bh = __float2bfloat16_rn(f);
    float r = f - __bfloat162float(bh);
    __nv_bfloat16 bl = __float2bfloat16_rn(r);
    h = *(uint16_t*)&bh;
    l = *(uint16_t*)&bl;
}
__device__ __forceinline__ void split_store4(char* hp, char* lp, float4 v) {
    uint16_t h0, h1, h2, h3, l0, l1, l2, l3;
    bf_split(v.x, h0, l0); bf_split(v.y, h1, l1);
    bf_split(v.z, h2, l2); bf_split(v.w, h3, l3);
    *(uint2*)hp = make_uint2((uint32_t)h0 | ((uint32_t)h1 << 16),
                             (uint32_t)h2 | ((uint32_t)h3 << 16));
    *(uint2*)lp = make_uint2((uint32_t)l0 | ((uint32_t)l1 << 16),
                             (uint32_t)l2 | ((uint32_t)l3 << 16));
}
__device__ __forceinline__ void cp16(uint32_t smem, const void* g) {
    asm volatile("cp.async.cg.shared.global [%0], [%1], 16;" :: "r"(smem), "l"(g));
}

// ------- kernel: fused setup (attn + prep + pack + packE), block-ranged ------
__global__ void __launch_bounds__(256)
setup_kernel(const float* __restrict__ x, const int* __restrict__ spk,
             const float* __restrict__ Wp1, const float* __restrict__ Ws1,
             const float* __restrict__ Wsa1, const float* __restrict__ Wd1,
             const float* __restrict__ Wag1,
             const float* __restrict__ Wp2, const float* __restrict__ Ws2,
             const float* __restrict__ Wsa2, const float* __restrict__ Wd2,
             const float* __restrict__ Wag2,
             const float* __restrict__ we1) {
    int blk = blockIdx.x;
    int tid = threadIdx.x;

    if (blk < SB_ATTN) {
        int warp = tid >> 5, lane = tid & 31;
        int i = blk * 8 + warp;

        float xi0 = x[i * DIM + lane];
        float xi1 = x[i * DIM + 32 + lane];
        float xi2 = x[i * DIM + 64 + lane];
        float xi3 = x[i * DIM + 96 + lane];

        float myscore = -3.4e38f;
        #pragma unroll
        for (int l = 0; l < BANDW; l++) {
            int j = i - WINSZ + l;
            if (j >= 0 && j < NROWS) {
                const float* xj = x + (size_t)j * DIM;
                float s = xi0 * xj[lane] + xi1 * xj[32 + lane]
                        + xi2 * xj[64 + lane] + xi3 * xj[96 + lane];
                #pragma unroll
                for (int off = 16; off; off >>= 1) s += __shfl_xor_sync(~0u, s, off);
                if (lane == l) myscore = s;
            }
        }
        int jl = i - WINSZ + lane;
        bool valid = (lane < BANDW) && (jl >= 0) && (jl < NROWS);
        float m = valid ? myscore : -3.4e38f;
        #pragma unroll
        for (int off = 16; off; off >>= 1) m = fmaxf(m, __shfl_xor_sync(~0u, m, off));
        m = fmaxf(m, 0.0f);
        float e = valid ? expf(myscore - m) : 0.0f;
        float sum = e;
        #pragma unroll
        for (int off = 16; off; off >>= 1) sum += __shfl_xor_sync(~0u, sum, off);
        int lo = max(0, i - WINSZ), hi = min(NROWS - 1, i + WINSZ);
        int nband = hi - lo + 1;
        float den = sum + (float)(NROWS - nband) * expf(-m);
        if (lane < BANDW) {
            g_attn[i * BANDW + lane] = valid ? (e / den) : 0.0f;
            int off = 0;
            if (valid) {
                bool same = (spk[jl] == spk[i]);
                bool pred = (lane >= WINSZ);
                int col = same ? (pred ? 0 : 1) : (pred ? 2 : 3);
                off = jl * YCOLS + col * DIM;
            }
            g_off[i * BANDW + lane] = off;
        }
    } else if (blk < SB_ATTN + SB_PREP) {
        int t = (blk - SB_ATTN) * 256 + tid;
        int i = t >> 5, q = t & 31;
        float4 v = ((const float4*)x)[t];
        size_t e = (size_t)i * 2 * DIM + DIM + q * 4;
        *(float4*)&g_Hcat[e] = v;
        split_store4((char*)g_Hh + e * 2, (char*)g_Hl + e * 2, v);
    } else if (blk < SB_ATTN + SB_PREP + SB_PACK) {
        int idx = (blk - SB_ATTN - SB_PREP) * 256 + tid;
        int n = idx >> 7, k = idx & 127;
        int rel = n >> 7, d = n & 127;
        const float* s1;
        const float* s2;
        switch (rel) {
            case 0: s1 = Wp1;  s2 = Wp2;  break;
            case 1: s1 = Ws1;  s2 = Ws2;  break;
            case 2: s1 = Wsa1; s2 = Wsa2; break;
            case 3: s1 = Wd1;  s2 = Wd2;  break;
            default: s1 = Wag1; s2 = Wag2; break;
        }
        uint16_t h, l;
        bf_split(s1[k * DIM + d], h, l);
        *(uint16_t*)&g_Bh1[idx] = h;
        *(uint16_t*)&g_Bl1[idx] = l;
        bf_split(s2[k * DIM + d], h, l);
        *(uint16_t*)&g_Bh2[idx] = h;
        *(uint16_t*)&g_Bl2[idx] = l;
    } else {
        int idx = (blk - SB_ATTN - SB_PREP - SB_PACK) * 256 + tid;
        int n = idx >> 8, k = idx & 255;
        uint16_t h, l;
        bf_split(we1[k * DIM + n], h, l);
        *(uint16_t*)&g_Weh[idx] = h;
        *(uint16_t*)&g_Wel[idx] = l;
    }
}

// ------- kernel: wmma bf16-split GEMM, cp.async k-pipeline -------------------
// NSTAGE 64-wide k-stages. grid (n_tiles, m_tiles), 8 warps (4m x 2n), 32x32/warp.
template <int NSTAGE, bool EPI>
__global__ void __launch_bounds__(256, 2)
wgemm_kernel(const __nv_bfloat16* __restrict__ Ah, const __nv_bfloat16* __restrict__ Al,
             int lda4,
             const __nv_bfloat16* __restrict__ Bh, const __nv_bfloat16* __restrict__ Bl,
             int ldb4,
             float* __restrict__ C, int ldc, const float* __restrict__ bias) {
    extern __shared__ __nv_bfloat16 sm[];

    int tid = threadIdx.x;
    int ntile = blockIdx.x, mtile = blockIdx.y;
    int warp = tid >> 5, lane = tid & 31;
    int wm = warp & 3;
    int wn = warp >> 2;

    int r0 = tid >> 3, q = tid & 7;     // per-thread copy coords (row base, float4 col)
    uint32_t smem_base = (uint32_t)__cvta_generic_to_shared(sm);

    // issue one stage's cp.async copies (stage s -> buffer b)
    auto load_stage = [&](int s, int b) {
        uint32_t st = smem_base + b * (ST_ELEMS * 2);
        const float4* gah = (const float4*)Ah;
        const float4* gal = (const float4*)Al;
        const float4* gbh = (const float4*)Bh;
        const float4* gbl = (const float4*)Bl;
        #pragma unroll
        for (int it = 0; it < 4; it++) {
            int row = r0 + it * 32;
            uint32_t so = (uint32_t)(row * LP + q * 8) * 2;    // 144B rows: 16B aligned
            int gi = (mtile * MT + row) * lda4 + s * 8 + q;
            cp16(st + ST_AH * 2 + so, gah + gi);
            cp16(st + ST_AL * 2 + so, gal + gi);
        }
        #pragma unroll
        for (int it = 0; it < 2; it++) {
            int row = r0 + it * 32;
            uint32_t so = (uint32_t)(row * LP + q * 8) * 2;
            int gi = (ntile * NT + row) * ldb4 + s * 8 + q;
            cp16(st + ST_BH * 2 + so, gbh + gi);
            cp16(st + ST_BL * 2 + so, gbl + gi);
        }
        asm volatile("cp.async.commit_group;");
    };

    wmma::fragment<wmma::accumulator, 16, 16, 16, float> acc[2][2];
    #pragma unroll
    for (int u = 0; u < 2; u++)
        #pragma unroll
        for (int v = 0; v < 2; v++) wmma::fill_fragment(acc[u][v], 0.0f);

    load_stage(0, 0);
    if (NSTAGE > 1) load_stage(1, 1);

    #pragma unroll
    for (int s = 0; s < NSTAGE; s++) {
        if (s + 1 < NSTAGE) asm volatile("cp.async.wait_group 1;");
        else                asm volatile("cp.async.wait_group 0;");
        __syncthreads();

        __nv_bfloat16* Ah_s = sm + (s & 1) * ST_ELEMS + ST_AH;
        __nv_bfloat16* Al_s = sm + (s & 1) * ST_ELEMS + ST_AL;
        __nv_bfloat16* Bh_s = sm + (s & 1) * ST_ELEMS + ST_BH;
        __nv_bfloat16* Bl_s = sm + (s & 1) * ST_ELEMS + ST_BL;

        #pragma unroll
        for (int ks = 0; ks < 4; ks++) {
            wmma::fragment<wmma::matrix_a, 16, 16, 16, __nv_bfloat16, wmma::row_major> ah[2], al[2];
            wmma::fragment<wmma::matrix_b, 16, 16, 16, __nv_bfloat16, wmma::col_major> bh[2], bl[2];
            #pragma unroll
            for (int u = 0; u < 2; u++) {
                int r = wm * 32 + u * 16;
                wmma::load_matrix_sync(ah[u], &Ah_s[r * LP + ks * 16], LP);
                wmma::load_matrix_sync(al[u], &Al_s[r * LP + ks * 16], LP);
            }
            #pragma unroll
            for (int v = 0; v < 2; v++) {
                int r = wn * 32 + v * 16;
                wmma::load_matrix_sync(bh[v], &Bh_s[r * LP + ks * 16], LP);
                wmma::load_matrix_sync(bl[v], &Bl_s[r * LP + ks * 16], LP);
            }
            #pragma unroll
            for (int u = 0; u < 2; u++)
                #pragma unroll
                for (int v = 0; v < 2; v++) {
                    wmma::mma_sync(acc[u][v], ah[u], bh[v], acc[u][v]);
                    wmma::mma_sync(acc[u][v], ah[u], bl[v], acc[u][v]);
                    wmma::mma_sync(acc[u][v], al[u], bh[v], acc[u][v]);
                }
        }

        if (s + 2 < NSTAGE) {
            __syncthreads();              // all reads of buffer (s&1) done
            load_stage(s + 2, s & 1);
        }
    }

    if (!EPI) {
        #pragma unroll
        for (int u = 0; u < 2; u++)
            #pragma unroll
            for (int v = 0; v < 2; v++) {
                int row = mtile * MT + wm * 32 + u * 16;
                int col = ntile * NT + wn * 32 + v * 16;
                wmma::store_matrix_sync(&C[(size_t)row * ldc + col], acc[u][v],
                                        ldc, wmma::mem_row_major);
            }
    } else {
        __syncthreads();
        float* stage = (float*)sm + warp * 1024;
        #pragma unroll
        for (int u = 0; u < 2; u++)
            #pragma unroll
            for (int v = 0; v < 2; v++)
                wmma::store_matrix_sync(&stage[u * 16 * 32 + v * 16], acc[u][v],
                                        32, wmma::mem_row_major);
        int row = mtile * MT + wm * 32 + lane;
        int colbase = ntile * NT + wn * 32;
        #pragma unroll
        for (int c = 0; c < 32; c += 4) {
            float4 val = *(float4*)&stage[lane * 32 + c];
            float4 bv = *(const float4*)&bias[colbase + c];
            val.x = fmaxf(val.x + bv.x, 0.0f);
            val.y = fmaxf(val.y + bv.y, 0.0f);
            val.z = fmaxf(val.z + bv.z, 0.0f);
            val.w = fmaxf(val.w + bv.w, 0.0f);
            *(float4*)&C[(size_t)row * ldc + colbase + c] = val;
        }
    }
}

// ------- kernel: banded combine + aggr + relu (warp/row, broadcast a/off) ----
template <int MODE>
__global__ void combine_kernel() {
    int warp = threadIdx.x >> 5, lane = threadIdx.x & 31;
    int i = blockIdx.x * 8 + warp;
    if (i >= NROWS) return;

    const float* arow = g_attn + i * BANDW;
    const int* orow = g_off + i * BANDW;
    const float4* Yv = (const float4*)g_Y;

    float da = arow[WINSZ];
    float4 yv = Yv[(i * YCOLS + 4 * DIM) / 4 + lane];
    float4 acc = make_float4(da * yv.x, da * yv.y, da * yv.z, da * yv.w);

    #pragma unroll
    for (int l = 0; l < BANDW; l++) {
        float a = arow[l];
        int off = orow[l];
        float4 y = Yv[off / 4 + lane];
        acc.x += a * y.x; acc.y += a * y.y;
        acc.z += a * y.z; acc.w += a * y.w;
    }
    acc.x = fmaxf(acc.x, 0.0f); acc.y = fmaxf(acc.y, 0.0f);
    acc.z = fmaxf(acc.z, 0.0f); acc.w = fmaxf(acc.w, 0.0f);

    if (MODE == 0) {
        size_t e = (size_t)i * DIM + lane * 4;
        split_store4((char*)g_Ah + e * 2, (char*)g_Al + e * 2, acc);
    } else {
        size_t e = (size_t)i * 2 * DIM + lane * 4;
        *(float4*)&g_Hcat[e] = acc;
        split_store4((char*)g_Hh + e * 2, (char*)g_Hl + e * 2, acc);
    }
}

// ---------------- kernel: emotion / sentiment heads --------------------------
__global__ void head_kernel(const float* __restrict__ we2, const float* __restrict__ be2,
                            const float* __restrict__ ws, const float* __restrict__ bs,
                            float* __restrict__ out) {
    int warp = threadIdx.x >> 5, lane = threadIdx.x & 31;
    int i = blockIdx.x * 8 + warp;
    if (i >= NROWS) return;

    float tv[4];
    #pragma unroll
    for (int c = 0; c < 4; c++) tv[c] = g_T[i * DIM + c * 32 + lane];
    float hv[8];
    #pragma unroll
    for (int c = 0; c < 8; c++) hv[c] = g_Hcat[i * 2 * DIM + c * 32 + lane];

    #pragma unroll
    for (int e = 0; e < NEMO; e++) {
        float s = 0.0f;
        #pragma unroll
        for (int c = 0; c < 4; c++) s += tv[c] * we2[(c * 32 + lane) * NEMO + e];
        #pragma unroll
        for (int off = 16; off; off >>= 1) s += __shfl_xor_sync(~0u, s, off);

        float s2 = 0.0f;
        #pragma unroll
        for (int c = 0; c < 8; c++) s2 += hv[c] * ws[(c * 32 + lane) * NEMO + e];
        #pragma unroll
        for (int off = 16; off; off >>= 1) s2 += __shfl_xor_sync(~0u, s2, off);

        if (lane == 0) {
            out[i * NEMO + e] = s + be2[e];
            out[NROWS * NEMO + i * NEMO + e] = s2 + bs[e];
        }
    }
}

// -----------------------------------------------------------------------------
extern "C" void kernel_launch(void* const* d_in, const int* in_sizes, int n_in,
                              void* d_out, int out_size) {
    const float* x       = (const float*)d_in[0];
    const int*   spk     = (const int*)d_in[1];
    const float* Wp1     = (const float*)d_in[2];
    const float* Ws1     = (const float*)d_in[3];
    const float* Wsa1    = (const float*)d_in[4];
    const float* Wd1     = (const float*)d_in[5];
    const float* Wp2     = (const float*)d_in[6];
    const float* Ws2     = (const float*)d_in[7];
    const float* Wsa2    = (const float*)d_in[8];
    const float* Wd2     = (const float*)d_in[9];
    const float* Wag1    = (const float*)d_in[10];
    const float* Wag2    = (const float*)d_in[11];
    const float* we1     = (const float*)d_in[12];
    const float* be1     = (const float*)d_in[13];
    const float* we2     = (const float*)d_in[14];
    const float* be2     = (const float*)d_in[15];
    const float* wsw     = (const float*)d_in[16];
    const float* bsb     = (const float*)d_in[17];
    float* out = (float*)d_out;

    cudaFuncSetAttribute(wgemm_kernel<2, false>,
                         cudaFuncAttributeMaxDynamicSharedMemorySize, WG_SMEM);
    cudaFuncSetAttribute(wgemm_kernel<4, true>,
                         cudaFuncAttributeMaxDynamicSharedMemorySize, WG_SMEM);

    __nv_bfloat16 *ah, *al, *hh, *hl, *bh1, *bl1, *bh2, *bl2, *weh, *wel;
    float *yp, *tp;
    cudaGetSymbolAddress((void**)&ah, g_Ah);
    cudaGetSymbolAddress((void**)&al, g_Al);
    cudaGetSymbolAddress((void**)&hh, g_Hh);
    cudaGetSymbolAddress((void**)&hl, g_Hl);
    cudaGetSymbolAddress((void**)&bh1, g_Bh1);
    cudaGetSymbolAddress((void**)&bl1, g_Bl1);
    cudaGetSymbolAddress((void**)&bh2, g_Bh2);
    cudaGetSymbolAddress((void**)&bl2, g_Bl2);
    cudaGetSymbolAddress((void**)&weh, g_Weh);
    cudaGetSymbolAddress((void**)&wel, g_Wel);
    cudaGetSymbolAddress((void**)&yp, g_Y);
    cudaGetSymbolAddress((void**)&tp, g_T);

    // 1. fused setup: attn + prep + pack + packE
    setup_kernel<<<SB_TOTAL, 256>>>(x, spk, Wp1, Ws1, Wsa1, Wd1, Wag1,
                                    Wp2, Ws2, Wsa2, Wd2, Wag2, we1);
    // 2. Y = x @ Wcat1   (A = right half of Hcat split; lda = 32 float4)
    wgemm_kernel<2, false><<<dim3(NTILES, MTILES), 256, WG_SMEM>>>(
        hh + DIM, hl + DIM, 32, bh1, bl1, 16, yp, YCOLS, nullptr);
    // 3. h1 = band-combine -> bf16 hi/lo
    combine_kernel<0><<<NROWS / 8, 256>>>();
    // 4. Y = h1 @ Wcat2
    wgemm_kernel<2, false><<<dim3(NTILES, MTILES), 256, WG_SMEM>>>(
        ah, al, 16, bh2, bl2, 16, yp, YCOLS, nullptr);
    // 5. h2 = band-combine -> Hcat left half + split
    combine_kernel<1><<<NROWS / 8, 256>>>();
    // 6. T = relu(Hcat @ we1 + be1)   (K = 256 -> 4 stages)
    wgemm_kernel<4, true><<<dim3(2, MTILES), 256, WG_SMEM>>>(
        hh, hl, 32, weh, wel, 32, tp, DIM, be1);
    // 7. heads
    head_kernel<<<NROWS / 8, 256>>>(we2, be2, wsw, bsb, out);
}